// round 7
// baseline (speedup 1.0000x reference)
#include <cuda_runtime.h>
#include <cuda_bf16.h>
#include <math_constants.h>
#include <cstdint>

// Problem constants
#define B_      4096
#define N_      4096
#define D_      512
#define GW      64
#define KT2     1536          // 3 tf32 planes * 512
#define KCH     32            // K per chunk (32 fp32 = 128B rows)
#define NCH     (KT2/KCH)     // 48 chunks
#define TM_     128
#define TN_     128
#define NCOLBLK (N_/TN_)      // 32
#define NSTAGE  3
#define STAGE_BYTES 32768     // A 16KB + B 16KB
#define SM_TOTAL (NSTAGE*STAGE_BYTES)   // 96 KB -> 2 CTAs/SM
#define NFULL   888           // 296 * 3 : perfectly packed waves
#define NGRID   (NFULL + 2*(1024 - NFULL))   // 888 + 272 = 1160

// Scratch globals
__device__ float g_xsq[B_];
__device__ float g_wsq[N_];
__device__ float g_pval[NCOLBLK * B_];
__device__ int   g_pidx[NCOLBLK * B_];
__device__ __align__(16) float g_A[(size_t)B_ * KT2];   // 24 MB
__device__ __align__(16) float g_B[(size_t)N_ * KT2];   // 24 MB

// ---------------------------------------------------------------------------
__device__ __forceinline__ uint32_t smem_to_u32(const void* p) {
    uint32_t a;
    asm("{ .reg .u64 t; cvta.to.shared.u64 t, %1; cvt.u32.u64 %0, t; }"
        : "=r"(a) : "l"(p));
    return a;
}

#define CP_ASYNC16(dst, src) \
    asm volatile("cp.async.cg.shared.global [%0], [%1], 16;" \
        :: "r"(dst), "l"(src) : "memory")
#define CP_COMMIT()  asm volatile("cp.async.commit_group;" ::: "memory")
#define CP_WAIT1()   asm volatile("cp.async.wait_group 1;"  ::: "memory")
#define CP_WAIT0()   asm volatile("cp.async.wait_group 0;"  ::: "memory")

#define LDSM4(r0, r1, r2, r3, addr) \
    asm volatile("ldmatrix.sync.aligned.m8n8.x4.shared.b16 {%0,%1,%2,%3}, [%4];" \
        : "=r"(r0), "=r"(r1), "=r"(r2), "=r"(r3) : "r"(addr))

#define MMA_TF32(d, a, b0v, b1v) \
    asm volatile("mma.sync.aligned.m16n8k8.row.col.f32.tf32.tf32.f32 " \
        "{%0,%1,%2,%3},{%4,%5,%6,%7},{%8,%9},{%0,%1,%2,%3};" \
        : "+f"((d)[0]), "+f"((d)[1]), "+f"((d)[2]), "+f"((d)[3]) \
        : "r"((a)[0]), "r"((a)[1]), "r"((a)[2]), "r"((a)[3]), \
          "r"(b0v), "r"(b1v))

__device__ __forceinline__ float tf32_rna(float x) {
    uint32_t u;
    asm("cvt.rna.tf32.f32 %0, %1;" : "=r"(u) : "f"(x));
    return __uint_as_float(u);
}

// ---------------------------------------------------------------------------
// Kernel 0: fused prep — sqsum + fp32->tf32 split planes in one pass.
// One warp per row (8192 warps). A planes [a0,a0,a1]; B planes [b0,b1,b0].
// ---------------------------------------------------------------------------
__global__ void prep_kernel(const float* __restrict__ X,
                            const float* __restrict__ Wt) {
    int warp = (blockIdx.x * blockDim.x + threadIdx.x) >> 5;
    int lane = threadIdx.x & 31;
    if (warp >= B_ + N_) return;
    const bool isW = warp >= B_;
    const int row = isW ? warp - B_ : warp;
    const float* src = isW ? Wt : X;
    float* dst = isW ? g_B : g_A;

    const float4* p = (const float4*)(src + (size_t)row * D_);
    float4* dbase = (float4*)(dst + (size_t)row * KT2);
    float s = 0.f;
    #pragma unroll
    for (int i = 0; i < 4; i++) {
        int v4 = lane + i * 32;            // float4 index within row (0..127)
        float4 v = p[v4];
        s = fmaf(v.x, v.x, s); s = fmaf(v.y, v.y, s);
        s = fmaf(v.z, v.z, s); s = fmaf(v.w, v.w, s);
        float4 a0, a1;
        a0.x = tf32_rna(v.x); a1.x = tf32_rna(v.x - a0.x);
        a0.y = tf32_rna(v.y); a1.y = tf32_rna(v.y - a0.y);
        a0.z = tf32_rna(v.z); a1.z = tf32_rna(v.z - a0.z);
        a0.w = tf32_rna(v.w); a1.w = tf32_rna(v.w - a0.w);
        dbase[v4] = a0;                         // plane 0 @ +0
        if (!isW) { dbase[v4 + 128] = a0; dbase[v4 + 256] = a1; }
        else      { dbase[v4 + 128] = a1; dbase[v4 + 256] = a0; }
    }
    #pragma unroll
    for (int o = 16; o; o >>= 1) s += __shfl_xor_sync(0xffffffffu, s, o);
    if (lane == 0) { if (isW) g_wsq[row] = s; else g_xsq[row] = s; }
}

// ---------------------------------------------------------------------------
// Stage loader: B always 128 rows; A rows runtime (128 full / 64 half).
// ---------------------------------------------------------------------------
__device__ __forceinline__ void load_stage(uint32_t sA, uint32_t sB,
                                           int arow0, int brow0, int kc0,
                                           int tid, int aRows) {
    for (int id = tid; id < aRows * 8; id += 256) {
        int m = id >> 3, ch = id & 7;
        int chs = ch ^ (m & 7);
        CP_ASYNC16(sA + m * 128 + chs * 16,
                   g_A + (size_t)(arow0 + m) * KT2 + kc0 + ch * 4);
    }
    #pragma unroll
    for (int it = 0; it < 4; it++) {
        int id = tid + it * 256;
        int n = id >> 3, ch = id & 7;
        int chs = ch ^ (n & 7);
        CP_ASYNC16(sB + n * 128 + chs * 16,
                   g_B + (size_t)(brow0 + n) * KT2 + kc0 + ch * 4);
    }
}

// ---------------------------------------------------------------------------
// GEMM + argmin tile body. MITERS=4 -> M=128 tile, MITERS=2 -> M=64 tile.
// 8 warps: 2 m-groups x 4 n-groups; warp tile (MITERS*16) x 32.
// ---------------------------------------------------------------------------
template<int MITERS>
__device__ __forceinline__ void gemm_tile(char* smem, uint32_t sb,
                                          int tid, int arow0, int colBlk) {
    const int wid = tid >> 5;
    const int l   = tid & 31;
    const int wm  = (wid >> 2) * (MITERS * 16);
    const int wn  = (wid & 3) * 32;
    const int brow0 = colBlk * TN_;
    const int aRows = MITERS * 32;

    const int mrow = (l & 7) + ((l >> 3) & 1) * 8;
    const int aAdd = l >> 4;
    const int nrow = (l & 7) + (l >> 4) * 8;
    const int bAdd = (l >> 3) & 1;

    uint32_t aRowOff[MITERS]; int aXr[MITERS];
    #pragma unroll
    for (int i = 0; i < MITERS; i++) {
        int r = wm + i * 16 + mrow;
        aRowOff[i] = r * 128; aXr[i] = r & 7;
    }
    uint32_t bRowOff[2]; int bXr[2];
    #pragma unroll
    for (int jj = 0; jj < 2; jj++) {
        int r = wn + jj * 16 + nrow;
        bRowOff[jj] = r * 128; bXr[jj] = r & 7;
    }

    float acc[MITERS][4][4];
    #pragma unroll
    for (int i = 0; i < MITERS; i++)
        #pragma unroll
        for (int j = 0; j < 4; j++)
            #pragma unroll
            for (int q = 0; q < 4; q++) acc[i][j][q] = 0.f;

    load_stage(sb, sb + 16384, arow0, brow0, 0, tid, aRows);
    CP_COMMIT();
    load_stage(sb + STAGE_BYTES, sb + STAGE_BYTES + 16384,
               arow0, brow0, KCH, tid, aRows);
    CP_COMMIT();

    for (int c = 0; c < NCH; c++) {
        CP_WAIT1();
        __syncthreads();

        if (c + 2 < NCH) {
            uint32_t st = sb + ((c + 2) % NSTAGE) * STAGE_BYTES;
            load_stage(st, st + 16384, arow0, brow0, (c + 2) * KCH, tid, aRows);
        }
        CP_COMMIT();

        const uint32_t Ab = sb + (c % NSTAGE) * STAGE_BYTES;
        const uint32_t Bb = Ab + 16384;

        #pragma unroll
        for (int ks = 0; ks < 4; ks++) {
            uint32_t ar[MITERS][4];
            #pragma unroll
            for (int i = 0; i < MITERS; i++)
                LDSM4(ar[i][0], ar[i][1], ar[i][2], ar[i][3],
                      Ab + aRowOff[i] + (uint32_t)(((ks * 2 + aAdd) ^ aXr[i]) * 16));
            uint32_t br[4][2];
            #pragma unroll
            for (int jj = 0; jj < 2; jj++) {
                uint32_t r0, r1, r2, r3;
                LDSM4(r0, r1, r2, r3,
                      Bb + bRowOff[jj] + (uint32_t)(((ks * 2 + bAdd) ^ bXr[jj]) * 16));
                br[jj * 2][0] = r0;      br[jj * 2][1] = r1;
                br[jj * 2 + 1][0] = r2;  br[jj * 2 + 1][1] = r3;
            }
            #pragma unroll
            for (int i = 0; i < MITERS; i++)
                #pragma unroll
                for (int j = 0; j < 4; j++)
                    MMA_TF32(acc[i][j], ar[i], br[j][0], br[j][1]);
        }
    }
    CP_WAIT0();
    __syncthreads();

    // ---- epilogue ----
    const int cbase = colBlk * TN_ + wn;
    float ws[4][2];
    #pragma unroll
    for (int j = 0; j < 4; j++) {
        ws[j][0] = g_wsq[cbase + j * 8 + (l & 3) * 2];
        ws[j][1] = g_wsq[cbase + j * 8 + (l & 3) * 2 + 1];
    }

    float* sVal = (float*)smem;
    int*   sIdx = (int*)(smem + 2048);

    #pragma unroll
    for (int i = 0; i < MITERS; i++) {
        #pragma unroll
        for (int h = 0; h < 2; h++) {
            int lrow = wm + i * 16 + h * 8 + (l >> 2);
            float xs = g_xsq[arow0 + lrow];
            float bv = CUDART_INF_F;
            int   bi = 0;
            #pragma unroll
            for (int j = 0; j < 4; j++) {
                #pragma unroll
                for (int q = 0; q < 2; q++) {
                    int col = cbase + j * 8 + (l & 3) * 2 + q;
                    float dot = acc[i][j][h * 2 + q];
                    float v = fmaxf((xs - 2.0f * dot) + ws[j][q], 0.0f);
                    if (v < bv) { bv = v; bi = col; }
                }
            }
            #pragma unroll
            for (int o = 1; o <= 2; o <<= 1) {
                float ov = __shfl_xor_sync(0xffffffffu, bv, o);
                int   oi = __shfl_xor_sync(0xffffffffu, bi, o);
                if (ov < bv || (ov == bv && oi < bi)) { bv = ov; bi = oi; }
            }
            if ((l & 3) == 0) {
                sVal[lrow * 4 + (wid & 3)] = bv;
                sIdx[lrow * 4 + (wid & 3)] = bi;
            }
        }
    }
    __syncthreads();

    if (tid < aRows) {
        float bv = sVal[tid * 4];
        int   bi = sIdx[tid * 4];
        #pragma unroll
        for (int t = 1; t < 4; t++) {
            float v = sVal[tid * 4 + t];
            int   ix = sIdx[tid * 4 + t];
            if (v < bv || (v == bv && ix < bi)) { bv = v; bi = ix; }
        }
        int gr = arow0 + tid;
        g_pval[colBlk * B_ + gr] = bv;
        g_pidx[colBlk * B_ + gr] = bi;
    }
}

// ---------------------------------------------------------------------------
// Kernel 2: bids 0..887 -> full 128x128 tiles (3 perfect waves at occ 2);
// bids 888..1159 -> 64x128 half tiles covering the remaining 136 tiles.
// ---------------------------------------------------------------------------
extern "C" __global__ void __launch_bounds__(256, 2)
dist_tc_kernel() {
    extern __shared__ char smem[];
    const uint32_t sb = smem_to_u32(smem);
    const int tid = threadIdx.x;
    const int bid = blockIdx.x;

    if (bid < NFULL) {
        int colBlk = bid & 31;
        int rowBlk = bid >> 5;
        gemm_tile<4>(smem, sb, tid, rowBlk * TM_, colBlk);
    } else {
        int e = bid - NFULL;                 // 0..271
        int t = NFULL + (e >> 1);            // tile id 888..1023
        int colBlk = t & 31;
        int rowBlk = t >> 5;
        int arow0 = rowBlk * TM_ + (e & 1) * 64;
        gemm_tile<2>(smem, sb, tid, arow0, colBlk);
    }
}

// ---------------------------------------------------------------------------
// Kernel 3: reduce the 32 column-block partials per row, emit outputs.
// ---------------------------------------------------------------------------
__global__ void finalize_kernel(float* __restrict__ out) {
    int warp = (blockIdx.x * blockDim.x + threadIdx.x) >> 5;
    int lane = threadIdx.x & 31;
    if (warp >= B_) return;

    float bv = g_pval[lane * B_ + warp];
    int   bi = g_pidx[lane * B_ + warp];
    #pragma unroll
    for (int o = 16; o; o >>= 1) {
        float ov = __shfl_xor_sync(0xffffffffu, bv, o);
        int   oi = __shfl_xor_sync(0xffffffffu, bi, o);
        if (ov < bv || (ov == bv && oi < bi)) { bv = ov; bi = oi; }
    }
    if (lane == 0) {
        out[warp * 2 + 0]  = (float)(bi >> 6);
        out[warp * 2 + 1]  = (float)(bi & (GW - 1));
        out[2 * B_ + warp] = sqrtf(bv);
    }
}

// ---------------------------------------------------------------------------
extern "C" void kernel_launch(void* const* d_in, const int* in_sizes, int n_in,
                              void* d_out, int out_size) {
    const float* X  = (const float*)d_in[0];
    const float* Wt = (const float*)d_in[1];
    float* out = (float*)d_out;

    cudaFuncSetAttribute(dist_tc_kernel,
                         cudaFuncAttributeMaxDynamicSharedMemorySize, SM_TOTAL);

    // 0) fused sqsum + tf32 split planes
    prep_kernel<<<(B_ + N_) / 8, 256>>>(X, Wt);

    // 1) tensor-core distance GEMM + per-tile argmin (split-tail grid)
    dist_tc_kernel<<<NGRID, 256, SM_TOTAL>>>();

    // 2) final reduction + outputs
    finalize_kernel<<<B_ / 8, 256>>>(out);
}

// round 9
// speedup vs baseline: 3.6357x; 3.6357x over previous
#include <cuda_runtime.h>
#include <cuda_bf16.h>
#include <math_constants.h>
#include <cstdint>

// Problem constants
#define B_      4096
#define N_      4096
#define D_      512
#define GW      64
#define KCH     32            // K per chunk (32 fp32 = 128B rows)
#define NCH     (D_/KCH)      // 16 chunks
#define TM_     128
#define TN_     128
#define NCOLBLK (N_/TN_)      // 32
#define NSTAGE  3
#define STAGE_BYTES 32768     // A 16KB + B 16KB
#define SM_TOTAL (NSTAGE*STAGE_BYTES)   // 96 KB -> 2 CTAs/SM
#define BAND    0.2f          // >> 2x worst-case tf32-truncation error on sq_dist
#define MAXCAND 128

// Scratch globals
__device__ float g_xsq[B_];
__device__ float g_wsq[N_];
__device__ float g_pval[NCOLBLK * B_];
__device__ __align__(16) float g_D[(size_t)B_ * N_];   // 64 MB coarse distances

// ---------------------------------------------------------------------------
__device__ __forceinline__ uint32_t smem_to_u32(const void* p) {
    uint32_t a;
    asm("{ .reg .u64 t; cvta.to.shared.u64 t, %1; cvt.u32.u64 %0, t; }"
        : "=r"(a) : "l"(p));
    return a;
}

#define CP_ASYNC16(dst, src) \
    asm volatile("cp.async.cg.shared.global [%0], [%1], 16;" \
        :: "r"(dst), "l"(src) : "memory")
#define CP_COMMIT()  asm volatile("cp.async.commit_group;" ::: "memory")
#define CP_WAIT1()   asm volatile("cp.async.wait_group 1;"  ::: "memory")
#define CP_WAIT0()   asm volatile("cp.async.wait_group 0;"  ::: "memory")

#define LDSM4(r0, r1, r2, r3, addr) \
    asm volatile("ldmatrix.sync.aligned.m8n8.x4.shared.b16 {%0,%1,%2,%3}, [%4];" \
        : "=r"(r0), "=r"(r1), "=r"(r2), "=r"(r3) : "r"(addr))

#define MMA_TF32(d, a, b0v, b1v) \
    asm volatile("mma.sync.aligned.m16n8k8.row.col.f32.tf32.tf32.f32 " \
        "{%0,%1,%2,%3},{%4,%5,%6,%7},{%8,%9},{%0,%1,%2,%3};" \
        : "+f"((d)[0]), "+f"((d)[1]), "+f"((d)[2]), "+f"((d)[3]) \
        : "r"((a)[0]), "r"((a)[1]), "r"((a)[2]), "r"((a)[3]), \
          "r"(b0v), "r"(b1v))

// ---------------------------------------------------------------------------
// Kernel 1: row sum-of-squares (fp32 originals)
// ---------------------------------------------------------------------------
__global__ void sqsum_kernel(const float* __restrict__ X,
                             const float* __restrict__ Wt) {
    int warp = (blockIdx.x * blockDim.x + threadIdx.x) >> 5;
    int lane = threadIdx.x & 31;
    if (warp >= B_ + N_) return;
    const float* src = (warp < B_) ? X : Wt;
    int row = (warp < B_) ? warp : (warp - B_);
    const float* p = src + (size_t)row * D_;
    float s = 0.f;
    #pragma unroll 4
    for (int i = lane; i < D_; i += 32) { float v = p[i]; s = fmaf(v, v, s); }
    #pragma unroll
    for (int o = 16; o; o >>= 1) s += __shfl_xor_sync(0xffffffffu, s, o);
    if (lane == 0) { if (warp < B_) g_xsq[row] = s; else g_wsq[row] = s; }
}

// ---------------------------------------------------------------------------
// Kernel 2: COARSE tf32 GEMM (M=128, N=128, K=512) on RAW fp32 inputs
// (hardware truncates to tf32). Writes full coarse distance matrix g_D
// + per-(row, colblock) coarse min partials. R5-proven structure: 8 warps,
// 64x32 warp tile, 3-stage cp.async, 2 CTAs/SM.
// ---------------------------------------------------------------------------
__device__ __forceinline__ void load_stage(uint32_t sA, uint32_t sB,
                                           const float* __restrict__ gA,
                                           const float* __restrict__ gB,
                                           int arow0, int brow0, int kc0,
                                           int tid) {
    #pragma unroll
    for (int it = 0; it < 4; it++) {
        int id = tid + it * 256;
        int m = id >> 3, ch = id & 7;
        int chs = ch ^ (m & 7);
        CP_ASYNC16(sA + m * 128 + chs * 16,
                   gA + (size_t)(arow0 + m) * D_ + kc0 + ch * 4);
    }
    #pragma unroll
    for (int it = 0; it < 4; it++) {
        int id = tid + it * 256;
        int n = id >> 3, ch = id & 7;
        int chs = ch ^ (n & 7);
        CP_ASYNC16(sB + n * 128 + chs * 16,
                   gB + (size_t)(brow0 + n) * D_ + kc0 + ch * 4);
    }
}

extern "C" __global__ void __launch_bounds__(256, 2)
dist_tc_kernel(const float* __restrict__ X, const float* __restrict__ Wt) {
    extern __shared__ char smem[];
    const uint32_t sb = smem_to_u32(smem);
    const int tid = threadIdx.x;
    const int wid = tid >> 5;
    const int l   = tid & 31;
    const int rowBlk = blockIdx.y;
    const int colBlk = blockIdx.x;

    const int wm = (wid >> 2) * 64;
    const int wn = (wid & 3) * 32;
    const int arow0 = rowBlk * TM_;
    const int brow0 = colBlk * TN_;

    const int mrow = (l & 7) + ((l >> 3) & 1) * 8;
    const int aAdd = l >> 4;
    const int nrow = (l & 7) + (l >> 4) * 8;
    const int bAdd = (l >> 3) & 1;

    uint32_t aRowOff[4]; int aXr[4];
    #pragma unroll
    for (int i = 0; i < 4; i++) {
        int r = wm + i * 16 + mrow;
        aRowOff[i] = r * 128; aXr[i] = r & 7;
    }
    uint32_t bRowOff[2]; int bXr[2];
    #pragma unroll
    for (int jj = 0; jj < 2; jj++) {
        int r = wn + jj * 16 + nrow;
        bRowOff[jj] = r * 128; bXr[jj] = r & 7;
    }

    float acc[4][4][4];
    #pragma unroll
    for (int i = 0; i < 4; i++)
        #pragma unroll
        for (int j = 0; j < 4; j++)
            #pragma unroll
            for (int q = 0; q < 4; q++) acc[i][j][q] = 0.f;

    load_stage(sb, sb + 16384, X, Wt, arow0, brow0, 0, tid);
    CP_COMMIT();
    load_stage(sb + STAGE_BYTES, sb + STAGE_BYTES + 16384,
               X, Wt, arow0, brow0, KCH, tid);
    CP_COMMIT();

    for (int c = 0; c < NCH; c++) {
        CP_WAIT1();
        __syncthreads();

        if (c + 2 < NCH) {
            uint32_t st = sb + ((c + 2) % NSTAGE) * STAGE_BYTES;
            load_stage(st, st + 16384, X, Wt, arow0, brow0, (c + 2) * KCH, tid);
        }
        CP_COMMIT();

        const uint32_t Ab = sb + (c % NSTAGE) * STAGE_BYTES;
        const uint32_t Bb = Ab + 16384;

        #pragma unroll
        for (int ks = 0; ks < 4; ks++) {
            uint32_t ar[4][4];
            #pragma unroll
            for (int i = 0; i < 4; i++)
                LDSM4(ar[i][0], ar[i][1], ar[i][2], ar[i][3],
                      Ab + aRowOff[i] + (uint32_t)(((ks * 2 + aAdd) ^ aXr[i]) * 16));
            uint32_t br[4][2];
            #pragma unroll
            for (int jj = 0; jj < 2; jj++) {
                uint32_t r0, r1, r2, r3;
                LDSM4(r0, r1, r2, r3,
                      Bb + bRowOff[jj] + (uint32_t)(((ks * 2 + bAdd) ^ bXr[jj]) * 16));
                br[jj * 2][0] = r0;      br[jj * 2][1] = r1;
                br[jj * 2 + 1][0] = r2;  br[jj * 2 + 1][1] = r3;
            }
            #pragma unroll
            for (int i = 0; i < 4; i++)
                #pragma unroll
                for (int j = 0; j < 4; j++)
                    MMA_TF32(acc[i][j], ar[i], br[j][0], br[j][1]);
        }
    }
    CP_WAIT0();
    __syncthreads();

    // ---- epilogue: coarse distances -> g_D + per-tile min partials ----
    const int cbase = colBlk * TN_ + wn;
    float ws[4][2];
    #pragma unroll
    for (int j = 0; j < 4; j++) {
        ws[j][0] = g_wsq[cbase + j * 8 + (l & 3) * 2];
        ws[j][1] = g_wsq[cbase + j * 8 + (l & 3) * 2 + 1];
    }

    float* sVal = (float*)smem;            // [128][4]

    #pragma unroll
    for (int i = 0; i < 4; i++) {
        #pragma unroll
        for (int h = 0; h < 2; h++) {
            int lrow = wm + i * 16 + h * 8 + (l >> 2);
            int grow = arow0 + lrow;
            float xs = g_xsq[grow];
            float bv = CUDART_INF_F;
            #pragma unroll
            for (int j = 0; j < 4; j++) {
                float2 vv;
                vv.x = fmaxf((xs - 2.0f * acc[i][j][h * 2 + 0]) + ws[j][0], 0.0f);
                vv.y = fmaxf((xs - 2.0f * acc[i][j][h * 2 + 1]) + ws[j][1], 0.0f);
                bv = fminf(bv, fminf(vv.x, vv.y));
                *(float2*)&g_D[(size_t)grow * N_ + cbase + j * 8 + (l & 3) * 2] = vv;
            }
            #pragma unroll
            for (int o = 1; o <= 2; o <<= 1)
                bv = fminf(bv, __shfl_xor_sync(0xffffffffu, bv, o));
            if ((l & 3) == 0) sVal[lrow * 4 + (wid & 3)] = bv;
        }
    }
    __syncthreads();

    if (tid < TM_) {
        float bv = fminf(fminf(sVal[tid * 4], sVal[tid * 4 + 1]),
                         fminf(sVal[tid * 4 + 2], sVal[tid * 4 + 3]));
        g_pval[colBlk * B_ + arow0 + tid] = bv;
    }
}

// ---------------------------------------------------------------------------
// Kernel 3: per-row refine. Reduce coarse min, scan the row of g_D for
// candidates within BAND, recompute those exactly in fp32, emit outputs.
// One CTA of 128 threads per row.
// ---------------------------------------------------------------------------
__global__ void __launch_bounds__(128)
refine_kernel(const float* __restrict__ X, const float* __restrict__ Wt,
              float* __restrict__ out) {
    const int row = blockIdx.x;
    const int tid = threadIdx.x;
    __shared__ float s_min;
    __shared__ int   s_cnt;
    __shared__ int   s_cand[MAXCAND];
    __shared__ float s_part[4];

    // 1) coarse row min from partials
    if (tid < 32) {
        float m = g_pval[tid * B_ + row];
        #pragma unroll
        for (int o = 16; o; o >>= 1)
            m = fminf(m, __shfl_xor_sync(0xffffffffu, m, o));
        if (tid == 0) { s_min = m; s_cnt = 0; }
    }
    __syncthreads();
    const float thresh = s_min + BAND;

    // 2) candidate scan over the coarse row
    const float* drow = g_D + (size_t)row * N_;
    for (int j = tid; j < N_; j += 128) {
        if (drow[j] < thresh) {
            int p = atomicAdd(&s_cnt, 1);
            if (p < MAXCAND) s_cand[p] = j;
        }
    }
    __syncthreads();
    const int cnt = min(s_cnt, MAXCAND);

    // 3) exact evaluation of candidates (fp32, matches R1-proven path)
    float xr[4];
    #pragma unroll
    for (int i = 0; i < 4; i++) xr[i] = X[(size_t)row * D_ + tid + i * 128];
    const float xs = g_xsq[row];

    float bestV = CUDART_INF_F;
    int   bestI = 0x7fffffff;
    for (int c = 0; c < cnt; c++) {
        int col = s_cand[c];
        const float* wrow = Wt + (size_t)col * D_;
        float part = 0.f;
        #pragma unroll
        for (int i = 0; i < 4; i++)
            part = fmaf(xr[i], wrow[tid + i * 128], part);
        #pragma unroll
        for (int o = 16; o; o >>= 1)
            part += __shfl_xor_sync(0xffffffffu, part, o);
        if ((tid & 31) == 0) s_part[tid >> 5] = part;
        __syncthreads();
        float dot = ((s_part[0] + s_part[1]) + s_part[2]) + s_part[3];
        float v = fmaxf((xs - 2.0f * dot) + g_wsq[col], 0.0f);
        if (v < bestV || (v == bestV && col < bestI)) { bestV = v; bestI = col; }
        __syncthreads();
    }

    if (tid == 0) {
        out[row * 2 + 0]  = (float)(bestI >> 6);
        out[row * 2 + 1]  = (float)(bestI & (GW - 1));
        out[2 * B_ + row] = sqrtf(bestV);
    }
}

// ---------------------------------------------------------------------------
extern "C" void kernel_launch(void* const* d_in, const int* in_sizes, int n_in,
                              void* d_out, int out_size) {
    const float* X  = (const float*)d_in[0];
    const float* Wt = (const float*)d_in[1];
    float* out = (float*)d_out;

    cudaFuncSetAttribute(dist_tc_kernel,
                         cudaFuncAttributeMaxDynamicSharedMemorySize, SM_TOTAL);

    // 1) row sum-of-squares
    sqsum_kernel<<<(B_ + N_) / 8, 256>>>(X, Wt);

    // 2) coarse tf32 distance GEMM (K=512, raw fp32 -> tf32 truncation)
    dim3 grid(N_ / TN_, B_ / TM_);   // (32, 32)
    dist_tc_kernel<<<grid, 256, SM_TOTAL>>>(X, Wt);

    // 3) per-row candidate refine + outputs
    refine_kernel<<<B_, 128>>>(X, Wt, out);
}

// round 10
// speedup vs baseline: 5.6202x; 1.5459x over previous
#include <cuda_runtime.h>
#include <cuda_bf16.h>
#include <math_constants.h>
#include <cstdint>

// Problem constants
#define B_      4096
#define N_      4096
#define D_      512
#define GW      64
#define KCH     64            // bf16 K per chunk (128B rows)
#define NCH     (D_/KCH)      // 8 chunks
#define TM_     128
#define TN_     128
#define NCOLBLK (N_/TN_)      // 32
#define NSTAGE  3
#define STAGE_BYTES 32768     // A 16KB + B 16KB
#define SM_TOTAL (NSTAGE*STAGE_BYTES)   // 96 KB -> 2 CTAs/SM
#define BAND    0.35f         // covers bf16 coarse error + bf16 store quantization
#define MAXCAND 128

// Scratch globals
__device__ float g_xsq[B_];
__device__ float g_wsq[N_];
__device__ float g_pval[NCOLBLK * B_];                     // per-tile min of c
__device__ __align__(16) __nv_bfloat16 g_Ab[(size_t)B_ * D_];   // 4 MB
__device__ __align__(16) __nv_bfloat16 g_Bb[(size_t)N_ * D_];   // 4 MB
__device__ __align__(16) __nv_bfloat16 g_Dc[(size_t)B_ * N_];   // 32 MB: c = wsq - 2*dot

// ---------------------------------------------------------------------------
__device__ __forceinline__ uint32_t smem_to_u32(const void* p) {
    uint32_t a;
    asm("{ .reg .u64 t; cvta.to.shared.u64 t, %1; cvt.u32.u64 %0, t; }"
        : "=r"(a) : "l"(p));
    return a;
}

#define CP_ASYNC16(dst, src) \
    asm volatile("cp.async.cg.shared.global [%0], [%1], 16;" \
        :: "r"(dst), "l"(src) : "memory")
#define CP_COMMIT()  asm volatile("cp.async.commit_group;" ::: "memory")
#define CP_WAIT1()   asm volatile("cp.async.wait_group 1;"  ::: "memory")
#define CP_WAIT0()   asm volatile("cp.async.wait_group 0;"  ::: "memory")

#define LDSM4(r0, r1, r2, r3, addr) \
    asm volatile("ldmatrix.sync.aligned.m8n8.x4.shared.b16 {%0,%1,%2,%3}, [%4];" \
        : "=r"(r0), "=r"(r1), "=r"(r2), "=r"(r3) : "r"(addr))

#define MMA_BF16(d, a, b0v, b1v) \
    asm volatile("mma.sync.aligned.m16n8k16.row.col.f32.bf16.bf16.f32 " \
        "{%0,%1,%2,%3},{%4,%5,%6,%7},{%8,%9},{%0,%1,%2,%3};" \
        : "+f"((d)[0]), "+f"((d)[1]), "+f"((d)[2]), "+f"((d)[3]) \
        : "r"((a)[0]), "r"((a)[1]), "r"((a)[2]), "r"((a)[3]), \
          "r"(b0v), "r"(b1v))

// ---------------------------------------------------------------------------
// Kernel 1: fused row sum-of-squares + fp32->bf16 conversion.
// One warp per row; warps < B_ -> X/g_Ab, else -> W/g_Bb.
// ---------------------------------------------------------------------------
__global__ void prep_kernel(const float* __restrict__ X,
                            const float* __restrict__ Wt) {
    int warp = (blockIdx.x * blockDim.x + threadIdx.x) >> 5;
    int lane = threadIdx.x & 31;
    if (warp >= B_ + N_) return;
    const bool isW = warp >= B_;
    const int row = isW ? warp - B_ : warp;
    const float* src = isW ? Wt : X;
    __nv_bfloat16* dst = isW ? g_Bb : g_Ab;

    const float4* p = (const float4*)(src + (size_t)row * D_);
    ushort4* d4 = (ushort4*)(dst + (size_t)row * D_);
    float s = 0.f;
    #pragma unroll
    for (int i = 0; i < 4; i++) {
        int v4 = lane + i * 32;
        float4 v = p[v4];
        s = fmaf(v.x, v.x, s); s = fmaf(v.y, v.y, s);
        s = fmaf(v.z, v.z, s); s = fmaf(v.w, v.w, s);
        ushort4 h;
        h.x = __bfloat16_as_ushort(__float2bfloat16_rn(v.x));
        h.y = __bfloat16_as_ushort(__float2bfloat16_rn(v.y));
        h.z = __bfloat16_as_ushort(__float2bfloat16_rn(v.z));
        h.w = __bfloat16_as_ushort(__float2bfloat16_rn(v.w));
        d4[v4] = h;
    }
    #pragma unroll
    for (int o = 16; o; o >>= 1) s += __shfl_xor_sync(0xffffffffu, s, o);
    if (lane == 0) { if (isW) g_wsq[row] = s; else g_xsq[row] = s; }
}

// ---------------------------------------------------------------------------
// Kernel 2: COARSE bf16 GEMM (M=128, N=128, K=512), m16n8k16.
// Writes c = wsq - 2*dot (bf16) to g_Dc + per-tile fp32 min partials.
// Structure identical to the verified R5/R8 kernel (same lane maps, same
// swizzle, same 3-stage cp.async, 2 CTAs/SM) — only dtype/MMA changed.
// ---------------------------------------------------------------------------
__device__ __forceinline__ void load_stage(uint32_t sA, uint32_t sB,
                                           int arow0, int brow0, int kc0,
                                           int tid) {
    #pragma unroll
    for (int it = 0; it < 4; it++) {
        int id = tid + it * 256;
        int m = id >> 3, ch = id & 7;
        int chs = ch ^ (m & 7);
        CP_ASYNC16(sA + m * 128 + chs * 16,
                   g_Ab + (size_t)(arow0 + m) * D_ + kc0 + ch * 8);
    }
    #pragma unroll
    for (int it = 0; it < 4; it++) {
        int id = tid + it * 256;
        int n = id >> 3, ch = id & 7;
        int chs = ch ^ (n & 7);
        CP_ASYNC16(sB + n * 128 + chs * 16,
                   g_Bb + (size_t)(brow0 + n) * D_ + kc0 + ch * 8);
    }
}

extern "C" __global__ void __launch_bounds__(256, 2)
dist_tc_kernel() {
    extern __shared__ char smem[];
    const uint32_t sb = smem_to_u32(smem);
    const int tid = threadIdx.x;
    const int wid = tid >> 5;
    const int l   = tid & 31;
    const int rowBlk = blockIdx.y;
    const int colBlk = blockIdx.x;

    const int wm = (wid >> 2) * 64;
    const int wn = (wid & 3) * 32;
    const int arow0 = rowBlk * TM_;
    const int brow0 = colBlk * TN_;

    // lane maps (verified in tf32 rounds; identical for bf16 16B chunks)
    const int mrow = (l & 7) + ((l >> 3) & 1) * 8;
    const int aAdd = l >> 4;
    const int nrow = (l & 7) + (l >> 4) * 8;
    const int bAdd = (l >> 3) & 1;

    uint32_t aRowOff[4]; int aXr[4];
    #pragma unroll
    for (int i = 0; i < 4; i++) {
        int r = wm + i * 16 + mrow;
        aRowOff[i] = r * 128; aXr[i] = r & 7;
    }
    uint32_t bRowOff[2]; int bXr[2];
    #pragma unroll
    for (int jj = 0; jj < 2; jj++) {
        int r = wn + jj * 16 + nrow;
        bRowOff[jj] = r * 128; bXr[jj] = r & 7;
    }

    float acc[4][4][4];
    #pragma unroll
    for (int i = 0; i < 4; i++)
        #pragma unroll
        for (int j = 0; j < 4; j++)
            #pragma unroll
            for (int q = 0; q < 4; q++) acc[i][j][q] = 0.f;

    load_stage(sb, sb + 16384, arow0, brow0, 0, tid);
    CP_COMMIT();
    load_stage(sb + STAGE_BYTES, sb + STAGE_BYTES + 16384,
               arow0, brow0, KCH, tid);
    CP_COMMIT();

    for (int c = 0; c < NCH; c++) {
        CP_WAIT1();
        __syncthreads();

        if (c + 2 < NCH) {
            uint32_t st = sb + ((c + 2) % NSTAGE) * STAGE_BYTES;
            load_stage(st, st + 16384, arow0, brow0, (c + 2) * KCH, tid);
        }
        CP_COMMIT();

        const uint32_t Ab = sb + (c % NSTAGE) * STAGE_BYTES;
        const uint32_t Bb = Ab + 16384;

        #pragma unroll
        for (int ks = 0; ks < 4; ks++) {       // 4x k16 within 64-col chunk
            uint32_t ar[4][4];
            #pragma unroll
            for (int i = 0; i < 4; i++)
                LDSM4(ar[i][0], ar[i][1], ar[i][2], ar[i][3],
                      Ab + aRowOff[i] + (uint32_t)(((ks * 2 + aAdd) ^ aXr[i]) * 16));
            uint32_t br[4][2];
            #pragma unroll
            for (int jj = 0; jj < 2; jj++) {
                uint32_t r0, r1, r2, r3;
                LDSM4(r0, r1, r2, r3,
                      Bb + bRowOff[jj] + (uint32_t)(((ks * 2 + bAdd) ^ bXr[jj]) * 16));
                br[jj * 2][0] = r0;      br[jj * 2][1] = r1;
                br[jj * 2 + 1][0] = r2;  br[jj * 2 + 1][1] = r3;
            }
            #pragma unroll
            for (int i = 0; i < 4; i++)
                #pragma unroll
                for (int j = 0; j < 4; j++)
                    MMA_BF16(acc[i][j], ar[i], br[j][0], br[j][1]);
        }
    }
    CP_WAIT0();
    __syncthreads();

    // ---- epilogue: c = wsq - 2*dot -> bf16 g_Dc + per-tile fp32 min ----
    const int cbase = colBlk * TN_ + wn;
    float ws[4][2];
    #pragma unroll
    for (int j = 0; j < 4; j++) {
        ws[j][0] = g_wsq[cbase + j * 8 + (l & 3) * 2];
        ws[j][1] = g_wsq[cbase + j * 8 + (l & 3) * 2 + 1];
    }

    float* sVal = (float*)smem;            // [128][4]

    #pragma unroll
    for (int i = 0; i < 4; i++) {
        #pragma unroll
        for (int h = 0; h < 2; h++) {
            int lrow = wm + i * 16 + h * 8 + (l >> 2);
            int grow = arow0 + lrow;
            float bv = CUDART_INF_F;
            #pragma unroll
            for (int j = 0; j < 4; j++) {
                float cx = ws[j][0] - 2.0f * acc[i][j][h * 2 + 0];
                float cy = ws[j][1] - 2.0f * acc[i][j][h * 2 + 1];
                bv = fminf(bv, fminf(cx, cy));
                __nv_bfloat162 hh;
                hh.x = __float2bfloat16_rn(cx);
                hh.y = __float2bfloat16_rn(cy);
                *(__nv_bfloat162*)&g_Dc[(size_t)grow * N_ + cbase + j * 8 + (l & 3) * 2] = hh;
            }
            #pragma unroll
            for (int o = 1; o <= 2; o <<= 1)
                bv = fminf(bv, __shfl_xor_sync(0xffffffffu, bv, o));
            if ((l & 3) == 0) sVal[lrow * 4 + (wid & 3)] = bv;
        }
    }
    __syncthreads();

    if (tid < TM_) {
        float bv = fminf(fminf(sVal[tid * 4], sVal[tid * 4 + 1]),
                         fminf(sVal[tid * 4 + 2], sVal[tid * 4 + 3]));
        g_pval[colBlk * B_ + arow0 + tid] = bv;
    }
}

// ---------------------------------------------------------------------------
// Kernel 3: per-row refine. Coarse min over partials, candidate scan over
// bf16 c-row, exact fp32 recompute of candidates, emit outputs.
// ---------------------------------------------------------------------------
__global__ void __launch_bounds__(128)
refine_kernel(const float* __restrict__ X, const float* __restrict__ Wt,
              float* __restrict__ out) {
    const int row = blockIdx.x;
    const int tid = threadIdx.x;
    __shared__ float s_min;
    __shared__ int   s_cnt;
    __shared__ int   s_cand[MAXCAND];
    __shared__ float s_part[4];

    // 1) coarse row min of c from partials
    if (tid < 32) {
        float m = g_pval[tid * B_ + row];
        #pragma unroll
        for (int o = 16; o; o >>= 1)
            m = fminf(m, __shfl_xor_sync(0xffffffffu, m, o));
        if (tid == 0) { s_min = m; s_cnt = 0; }
    }
    __syncthreads();
    const float thresh = s_min + BAND;

    // 2) candidate scan over bf16 c-row (2 values per uint32 load)
    const uint32_t* drow = (const uint32_t*)(g_Dc + (size_t)row * N_);
    #pragma unroll 4
    for (int j2 = tid; j2 < N_ / 2; j2 += 128) {
        uint32_t pk = drow[j2];
        __nv_bfloat162 hv = *(__nv_bfloat162*)&pk;
        float c0 = __bfloat162float(hv.x);
        float c1 = __bfloat162float(hv.y);
        if (c0 < thresh) { int p = atomicAdd(&s_cnt, 1); if (p < MAXCAND) s_cand[p] = j2 * 2; }
        if (c1 < thresh) { int p = atomicAdd(&s_cnt, 1); if (p < MAXCAND) s_cand[p] = j2 * 2 + 1; }
    }
    __syncthreads();
    const int cnt = min(s_cnt, MAXCAND);

    // 3) exact fp32 evaluation of candidates (reference rounding order)
    float xr[4];
    #pragma unroll
    for (int i = 0; i < 4; i++) xr[i] = X[(size_t)row * D_ + tid + i * 128];
    const float xs = g_xsq[row];

    float bestV = CUDART_INF_F;
    int   bestI = 0x7fffffff;
    for (int c = 0; c < cnt; c++) {
        int col = s_cand[c];
        const float* wrow = Wt + (size_t)col * D_;
        float part = 0.f;
        #pragma unroll
        for (int i = 0; i < 4; i++)
            part = fmaf(xr[i], wrow[tid + i * 128], part);
        #pragma unroll
        for (int o = 16; o; o >>= 1)
            part += __shfl_xor_sync(0xffffffffu, part, o);
        if ((tid & 31) == 0) s_part[tid >> 5] = part;
        __syncthreads();
        float dot = ((s_part[0] + s_part[1]) + s_part[2]) + s_part[3];
        float v = fmaxf((xs - 2.0f * dot) + g_wsq[col], 0.0f);
        if (v < bestV || (v == bestV && col < bestI)) { bestV = v; bestI = col; }
        __syncthreads();
    }

    if (tid == 0) {
        out[row * 2 + 0]  = (float)(bestI >> 6);
        out[row * 2 + 1]  = (float)(bestI & (GW - 1));
        out[2 * B_ + row] = sqrtf(bestV);
    }
}

// ---------------------------------------------------------------------------
extern "C" void kernel_launch(void* const* d_in, const int* in_sizes, int n_in,
                              void* d_out, int out_size) {
    const float* X  = (const float*)d_in[0];
    const float* Wt = (const float*)d_in[1];
    float* out = (float*)d_out;

    cudaFuncSetAttribute(dist_tc_kernel,
                         cudaFuncAttributeMaxDynamicSharedMemorySize, SM_TOTAL);

    // 1) fused sqsum + bf16 conversion
    prep_kernel<<<(B_ + N_) / 8, 256>>>(X, Wt);

    // 2) coarse bf16 distance GEMM (K=512, m16n8k16)
    dim3 grid(N_ / TN_, B_ / TM_);   // (32, 32)
    dist_tc_kernel<<<grid, 256, SM_TOTAL>>>();

    // 3) per-row candidate refine + outputs
    refine_kernel<<<B_, 128>>>(X, Wt, out);
}